// round 3
// baseline (speedup 1.0000x reference)
#include <cuda_runtime.h>
#include <cuda_bf16.h>
#include <stdint.h>

#define N_NODES 100000
#define IN_F 256
#define OUT_F 64

// Scratch for support = tanh(features @ weight)  [N, 64]
__device__ float g_support[(size_t)N_NODES * OUT_F];

// ---------------------------------------------------------------------------
// GEMM + tanh:  C[M,64] = act(A[M,256] @ W[256,64])
// Block tile 256x64, BK=16, 256 threads; per-thread 8x8 via f32x2 row pairs.
// Register-prefetch pipeline: LDG tile i+1 into regs BEFORE computing tile i,
// removing global-load latency from the per-iteration critical path.
// ---------------------------------------------------------------------------
#define BM 256
#define BK 16
#define AS_STRIDE 260          // 256 + 4 pad words
#define WD_K_STRIDE 160        // 8 groups * 20 words
#define WD_TX_STRIDE 20        // 16 used + 4 pad words (80B)

#define FMA_F32X2(d, a, b, c) \
    asm("fma.rn.f32x2 %0, %1, %2, %3;" : "=l"(d) : "l"(a), "l"(b), "l"(c))

__device__ __forceinline__ float f2_lo(unsigned long long x) {
    return __uint_as_float((unsigned)(x & 0xffffffffull));
}
__device__ __forceinline__ float f2_hi(unsigned long long x) {
    return __uint_as_float((unsigned)(x >> 32));
}

__global__ __launch_bounds__(256, 2) void gemm_tanh_kernel(
    const float* __restrict__ A, const float* __restrict__ W,
    const int* __restrict__ active, float* __restrict__ C, int M)
{
    __shared__ float s_as[BK * AS_STRIDE];   // ~16.6KB
    __shared__ float s_wd[BK * WD_K_STRIDE]; // 10.2KB

    const int tid = threadIdx.x;
    const int tx = tid & 7;           // col group: cols 8tx..8tx+7
    const int ty = tid >> 3;          // row group: rows 8ty..8ty+7
    const int row0 = blockIdx.x * BM;

    // staging-load index precompute (same every tile)
    const int a_r  = tid >> 2;               // 0..63 base (per i add 64)
    const int a_cq = (tid & 3) << 2;         // 0,4,8,12
    const int w_k  = tid >> 6;               // 0..3 base (per i add 4)
    const int w_n  = tid & 63;

    unsigned long long acc[4][8];
    #pragma unroll
    for (int rp = 0; rp < 4; rp++)
        #pragma unroll
        for (int j = 0; j < 8; j++) acc[rp][j] = 0ull;

    float4 pa[4];
    float  pw[4];

    // prefetch tile 0
    #pragma unroll
    for (int i = 0; i < 4; i++) {
        int gr = row0 + a_r + i * 64;
        pa[i] = make_float4(0.f, 0.f, 0.f, 0.f);
        if (gr < M)
            pa[i] = *reinterpret_cast<const float4*>(&A[(size_t)gr * IN_F + a_cq]);
        pw[i] = W[(size_t)(w_k + i * 4) * OUT_F + w_n];
    }

    for (int k0 = 0; k0 < IN_F; k0 += BK) {
        // --- store staged tile into smem ---
        #pragma unroll
        for (int i = 0; i < 4; i++) {
            int r = a_r + i * 64;
            s_as[(a_cq + 0) * AS_STRIDE + r] = pa[i].x;
            s_as[(a_cq + 1) * AS_STRIDE + r] = pa[i].y;
            s_as[(a_cq + 2) * AS_STRIDE + r] = pa[i].z;
            s_as[(a_cq + 3) * AS_STRIDE + r] = pa[i].w;
            float w = pw[i];
            *reinterpret_cast<float2*>(
                &s_wd[(w_k + i * 4) * WD_K_STRIDE
                      + (w_n >> 3) * WD_TX_STRIDE + ((w_n & 7) << 1)]) =
                make_float2(w, w);
        }
        __syncthreads();

        // --- prefetch next tile into regs (overlaps with compute below) ---
        if (k0 + BK < IN_F) {
            #pragma unroll
            for (int i = 0; i < 4; i++) {
                int gr = row0 + a_r + i * 64;
                pa[i] = make_float4(0.f, 0.f, 0.f, 0.f);
                if (gr < M)
                    pa[i] = *reinterpret_cast<const float4*>(
                        &A[(size_t)gr * IN_F + k0 + BK + a_cq]);
                pw[i] = W[(size_t)(k0 + BK + w_k + i * 4) * OUT_F + w_n];
            }
        }

        // --- compute 16 k-steps from smem ---
        const float* as_base = &s_as[ty << 3];
        const float* wd_base = &s_wd[tx * WD_TX_STRIDE];
        #pragma unroll
        for (int k = 0; k < BK; k++) {
            ulonglong2 a01 = *reinterpret_cast<const ulonglong2*>(&as_base[k * AS_STRIDE]);
            ulonglong2 a23 = *reinterpret_cast<const ulonglong2*>(&as_base[k * AS_STRIDE + 4]);
            const float* wr = &wd_base[k * WD_K_STRIDE];
            ulonglong2 b01 = *reinterpret_cast<const ulonglong2*>(&wr[0]);
            ulonglong2 b23 = *reinterpret_cast<const ulonglong2*>(&wr[4]);
            ulonglong2 b45 = *reinterpret_cast<const ulonglong2*>(&wr[8]);
            ulonglong2 b67 = *reinterpret_cast<const ulonglong2*>(&wr[12]);

            unsigned long long ap[4] = {a01.x, a01.y, a23.x, a23.y};
            unsigned long long bp[8] = {b01.x, b01.y, b23.x, b23.y,
                                        b45.x, b45.y, b67.x, b67.y};
            #pragma unroll
            for (int rp = 0; rp < 4; rp++) {
                #pragma unroll
                for (int j = 0; j < 8; j++) {
                    FMA_F32X2(acc[rp][j], ap[rp], bp[j], acc[rp][j]);
                }
            }
        }
        __syncthreads();   // all warps done reading before next STS
    }

    const int act = *active;
    const int ccol = tx << 3;
    #pragma unroll
    for (int rp = 0; rp < 4; rp++) {
        float vlo[8], vhi[8];
        #pragma unroll
        for (int j = 0; j < 8; j++) { vlo[j] = f2_lo(acc[rp][j]); vhi[j] = f2_hi(acc[rp][j]); }
        if (act) {
            #pragma unroll
            for (int j = 0; j < 8; j++) { vlo[j] = tanhf(vlo[j]); vhi[j] = tanhf(vhi[j]); }
        }
        int re = row0 + (ty << 3) + (rp << 1);
        if (re < M) {
            float4* dst = reinterpret_cast<float4*>(&C[(size_t)re * OUT_F + ccol]);
            dst[0] = make_float4(vlo[0], vlo[1], vlo[2], vlo[3]);
            dst[1] = make_float4(vlo[4], vlo[5], vlo[6], vlo[7]);
        }
        if (re + 1 < M) {
            float4* dst = reinterpret_cast<float4*>(&C[(size_t)(re + 1) * OUT_F + ccol]);
            dst[0] = make_float4(vhi[0], vhi[1], vhi[2], vhi[3]);
            dst[1] = make_float4(vhi[4], vhi[5], vhi[6], vhi[7]);
        }
    }
}

// ---------------------------------------------------------------------------
// SpMM: y[rows[e]] += vals[e] * x[cols[e]]   (rows sorted ascending)
// One warp per 128-edge chunk (4 rounds of 32); each lane owns 2 features.
// Register-accumulate runs of identical rows across rounds; flush via
// atomicAdd only on row change / chunk end.
// ---------------------------------------------------------------------------
#define EDGES_PER_WARP 128

__global__ __launch_bounds__(256) void spmm_kernel(
    const int* __restrict__ rows, const int* __restrict__ cols,
    const float* __restrict__ vals, const float* __restrict__ x,
    float* __restrict__ y, int nE)
{
    const int warp = (blockIdx.x * blockDim.x + threadIdx.x) >> 5;
    const int lane = threadIdx.x & 31;
    const int e0 = warp * EDGES_PER_WARP;
    if (e0 >= nE) return;

    const int f = lane << 1;   // feature pair owned by this lane
    float2 acc = make_float2(0.f, 0.f);
    int cur = rows[e0];        // first row of the chunk (uniform across warp)

    #pragma unroll
    for (int rnd = 0; rnd < EDGES_PER_WARP / 32; rnd++) {
        const int base = e0 + rnd * 32;
        if (base >= nE) break;
        const int n = min(32, nE - base);

        int   r = (lane < n) ? rows[base + lane] : -1;
        int   c = (lane < n) ? cols[base + lane] : 0;
        float v = (lane < n) ? vals[base + lane] : 0.0f;

        for (int i = 0; i < n; i++) {
            int   ri = __shfl_sync(0xffffffffu, r, i);
            int   ci = __shfl_sync(0xffffffffu, c, i);
            float vi = __shfl_sync(0xffffffffu, v, i);
            if (ri != cur) {
                float* dst = &y[(size_t)cur * OUT_F + f];
                atomicAdd(dst, acc.x);
                atomicAdd(dst + 1, acc.y);
                acc = make_float2(0.f, 0.f);
                cur = ri;
            }
            float2 xv = *reinterpret_cast<const float2*>(&x[(size_t)ci * OUT_F + f]);
            acc.x = fmaf(vi, xv.x, acc.x);
            acc.y = fmaf(vi, xv.y, acc.y);
        }
    }
    float* dst = &y[(size_t)cur * OUT_F + f];
    atomicAdd(dst, acc.x);
    atomicAdd(dst + 1, acc.y);
}

// ---------------------------------------------------------------------------
extern "C" void kernel_launch(void* const* d_in, const int* in_sizes, int n_in,
                              void* d_out, int out_size)
{
    const float* features = (const float*)d_in[0];   // [N, 256]
    const float* weight   = (const float*)d_in[1];   // [256, 64]
    const int*   adj_rows = (const int*)d_in[2];     // [E] sorted
    const int*   adj_cols = (const int*)d_in[3];     // [E]
    const float* adj_vals = (const float*)d_in[4];   // [E]
    const int*   active   = (const int*)d_in[5];     // scalar

    const int M  = in_sizes[0] / IN_F;               // 100000
    const int nE = in_sizes[2];                      // 1600000

    float* out_first  = (float*)d_out;                          // output [N,64]
    float* out_second = (float*)d_out + (size_t)M * OUT_F;      // az     [N,64]

    float* support = nullptr;
    cudaGetSymbolAddress((void**)&support, g_support);

    // zero both output halves (atomics accumulate into them)
    cudaMemsetAsync(d_out, 0, (size_t)out_size * sizeof(float), 0);

    // 1) support = tanh(features @ weight)
    int gblocks = (M + BM - 1) / BM;
    gemm_tanh_kernel<<<gblocks, 256>>>(features, weight, active, support, M);

    // 2) output = adj @ support
    int warps = (nE + EDGES_PER_WARP - 1) / EDGES_PER_WARP;
    int sblocks = (warps + 7) / 8;   // 8 warps per 256-thread block
    spmm_kernel<<<sblocks, 256>>>(adj_rows, adj_cols, adj_vals, support, out_first, nE);

    // 3) az = adj @ output
    spmm_kernel<<<sblocks, 256>>>(adj_rows, adj_cols, adj_vals, out_first, out_second, nE);
}

// round 5
// speedup vs baseline: 1.4726x; 1.4726x over previous
#include <cuda_runtime.h>
#include <cuda_bf16.h>
#include <stdint.h>

#define N_NODES 100000
#define IN_F 256
#define OUT_F 64

// Scratch for support = tanh(features @ weight)  [N, 64]
__device__ float g_support[(size_t)N_NODES * OUT_F];

// ===========================================================================
// GEMM + tanh via mma.sync bf16 3-product split (base ISA: works on sm_103).
//   A = A_hi + A_lo (bf16), W = W_hi + W_lo (bf16)
//   D = A_hi*W_hi + A_hi*W_lo + A_lo*W_hi   (error ~2^-17, tol is 1e-3)
// Block: 256 thr (8 warps), tile 128 rows x 64 cols, K in 2 chunks of 128.
// A in smem row-major bf16 (row stride 272B: conflict-free ldmatrix.x4).
// W pre-packed in smem in EXACT mma B-fragment order -> one LDS.64 per
// (kstep, ntile) per thread, fully coalesced/conflict-free.
// ===========================================================================
#define TILE_M 128
#define BKC 128                 // k-chunk
#define A_ROW_BYTES 272         // 128 bf16 = 256B + 16B pad
#define A_PART (TILE_M * A_ROW_BYTES)        // 34816
#define W_PART (8 * 8 * 32 * 8)              // 16384 (8 ksteps x 8 ntiles x 32 thr x 8B)
#define SM_AHI 0
#define SM_ALO (SM_AHI + A_PART)
#define SM_WHI (SM_ALO + A_PART)
#define SM_WLO (SM_WHI + W_PART)
#define SM_TOTAL_G (SM_WLO + W_PART)         // 102400 bytes -> 2 CTAs/SM

__device__ __forceinline__ uint32_t smem_u32(const void* p) {
    uint32_t a;
    asm("{ .reg .u64 t; cvta.to.shared.u64 t, %1; cvt.u32.u64 %0, t; }"
        : "=r"(a) : "l"(p));
    return a;
}

#define LDSM_X4(r, addr) \
    asm volatile("ldmatrix.sync.aligned.m8n8.x4.shared.b16 {%0,%1,%2,%3}, [%4];" \
        : "=r"((r)[0]), "=r"((r)[1]), "=r"((r)[2]), "=r"((r)[3]) : "r"(addr))

#define MMA_BF16(d, a, b0, b1) \
    asm volatile("mma.sync.aligned.m16n8k16.row.col.f32.bf16.bf16.f32 " \
        "{%0,%1,%2,%3}, {%4,%5,%6,%7}, {%8,%9}, {%0,%1,%2,%3};" \
        : "+f"((d)[0]), "+f"((d)[1]), "+f"((d)[2]), "+f"((d)[3]) \
        : "r"((a)[0]), "r"((a)[1]), "r"((a)[2]), "r"((a)[3]), "r"(b0), "r"(b1))

__device__ __forceinline__ uint32_t pack_hi2(float x, float y) {
    __nv_bfloat16 hx = __float2bfloat16(x), hy = __float2bfloat16(y);
    return (uint32_t)__bfloat16_as_ushort(hx) |
           ((uint32_t)__bfloat16_as_ushort(hy) << 16);
}
__device__ __forceinline__ uint32_t pack_lo2(float x, float y) {
    __nv_bfloat16 hx = __float2bfloat16(x), hy = __float2bfloat16(y);
    __nv_bfloat16 lx = __float2bfloat16(x - __bfloat162float(hx));
    __nv_bfloat16 ly = __float2bfloat16(y - __bfloat162float(hy));
    return (uint32_t)__bfloat16_as_ushort(lx) |
           ((uint32_t)__bfloat16_as_ushort(ly) << 16);
}

__global__ __launch_bounds__(256, 2) void gemm_mma_kernel(
    const float* __restrict__ A, const float* __restrict__ W,
    const int* __restrict__ active, float* __restrict__ C, int M)
{
    extern __shared__ char sm[];
    const uint32_t sb = smem_u32(sm);
    const int tid = threadIdx.x;
    const int wid = tid >> 5;
    const int lane = tid & 31;
    const int row0 = blockIdx.x * TILE_M;

    float d[8][4];
    #pragma unroll
    for (int j = 0; j < 8; j++)
        #pragma unroll
        for (int e = 0; e < 4; e++) d[j][e] = 0.f;

    // per-lane ldmatrix source address (within A tile, before k-step offset)
    const uint32_t a_lm_base =
        sb + SM_AHI + (uint32_t)(wid * 16 + (lane & 15)) * A_ROW_BYTES
        + (uint32_t)((lane >> 4) * 16);

    #pragma unroll
    for (int kc = 0; kc < 2; kc++) {
        const int kbase = kc * BKC;

        // ---- A chunk: 128 rows x 128 k (fp32 -> hi/lo bf16) ----
        #pragma unroll
        for (int i = 0; i < 16; i++) {
            int idx = tid + i * 256;         // 0..4095
            int r = idx >> 5;                // 0..127
            int q = idx & 31;                // float4 in row
            int gr = row0 + r;
            float4 v = make_float4(0.f, 0.f, 0.f, 0.f);
            if (gr < M)
                v = *reinterpret_cast<const float4*>(
                    &A[(size_t)gr * IN_F + kbase + (q << 2)]);
            uint2 hp = make_uint2(pack_hi2(v.x, v.y), pack_hi2(v.z, v.w));
            uint2 lp = make_uint2(pack_lo2(v.x, v.y), pack_lo2(v.z, v.w));
            int off = r * A_ROW_BYTES + q * 8;
            *reinterpret_cast<uint2*>(sm + SM_AHI + off) = hp;
            *reinterpret_cast<uint2*>(sm + SM_ALO + off) = lp;
        }

        // ---- W chunk: pack into mma B-fragment order ----
        // fragment (s,j,lane): b0={W[k][n],W[k+1][n]}, b1={W[k+8][n],W[k+9][n]}
        //   k = kbase + s*16 + (lane&3)*2 ; n = j*8 + (lane>>2)
        #pragma unroll
        for (int i = 0; i < 8; i++) {
            int idx = tid + i * 256;         // 0..2047
            int t = idx & 31;
            int j = (idx >> 5) & 7;
            int s = idx >> 8;                // 0..7
            int k = kbase + s * 16 + (t & 3) * 2;
            int n = j * 8 + (t >> 2);
            float w00 = W[(size_t)k * OUT_F + n];
            float w01 = W[(size_t)(k + 1) * OUT_F + n];
            float w10 = W[(size_t)(k + 8) * OUT_F + n];
            float w11 = W[(size_t)(k + 9) * OUT_F + n];
            *reinterpret_cast<uint2*>(sm + SM_WHI + idx * 8) =
                make_uint2(pack_hi2(w00, w01), pack_hi2(w10, w11));
            *reinterpret_cast<uint2*>(sm + SM_WLO + idx * 8) =
                make_uint2(pack_lo2(w00, w01), pack_lo2(w10, w11));
        }
        __syncthreads();

        // ---- MMA: 8 k16-steps x (hi*hi + hi*lo + lo*hi) ----
        #pragma unroll
        for (int s = 0; s < 8; s++) {
            uint32_t ah[4], al[4];
            LDSM_X4(ah, a_lm_base + s * 32);
            LDSM_X4(al, a_lm_base + s * 32 + (SM_ALO - SM_AHI));
            const char* whb = sm + SM_WHI + (s * 8 * 32 + lane) * 8;
            const char* wlb = sm + SM_WLO + (s * 8 * 32 + lane) * 8;
            #pragma unroll
            for (int j = 0; j < 8; j++) {
                uint2 bh = *reinterpret_cast<const uint2*>(whb + j * 256);
                uint2 bl = *reinterpret_cast<const uint2*>(wlb + j * 256);
                MMA_BF16(d[j], ah, bh.x, bh.y);
                MMA_BF16(d[j], al, bh.x, bh.y);
                MMA_BF16(d[j], ah, bl.x, bl.y);
            }
        }
        __syncthreads();
    }

    // ---- epilogue: tanh + store ----
    const int act = *active;
    int rlo = row0 + wid * 16 + (lane >> 2);
    int col = (lane & 3) * 2;
    #pragma unroll
    for (int j = 0; j < 8; j++) {
        float2 p0 = make_float2(d[j][0], d[j][1]);
        float2 p1 = make_float2(d[j][2], d[j][3]);
        if (act) {
            p0.x = tanhf(p0.x); p0.y = tanhf(p0.y);
            p1.x = tanhf(p1.x); p1.y = tanhf(p1.y);
        }
        if (rlo < M)
            *reinterpret_cast<float2*>(&C[(size_t)rlo * OUT_F + j * 8 + col]) = p0;
        if (rlo + 8 < M)
            *reinterpret_cast<float2*>(&C[(size_t)(rlo + 8) * OUT_F + j * 8 + col]) = p1;
    }
}

// ---------------------------------------------------------------------------
// SpMM: y[rows[e]] += vals[e] * x[cols[e]]   (rows sorted ascending)
// One warp per 32-edge chunk (R2 config — proven fastest); each lane owns
// 2 features. Register-accumulate runs, flush via atomicAdd on row change.
// ---------------------------------------------------------------------------
__global__ __launch_bounds__(256) void spmm_kernel(
    const int* __restrict__ rows, const int* __restrict__ cols,
    const float* __restrict__ vals, const float* __restrict__ x,
    float* __restrict__ y, int nE)
{
    const int warp = (blockIdx.x * blockDim.x + threadIdx.x) >> 5;
    const int lane = threadIdx.x & 31;
    const int e0 = warp * 32;
    if (e0 >= nE) return;
    const int n = min(32, nE - e0);

    int   r = (lane < n) ? rows[e0 + lane] : -1;
    int   c = (lane < n) ? cols[e0 + lane] : 0;
    float v = (lane < n) ? vals[e0 + lane] : 0.0f;

    const int f = lane << 1;
    float2 acc = make_float2(0.f, 0.f);
    int cur = __shfl_sync(0xffffffffu, r, 0);

    for (int i = 0; i < n; i++) {
        int   ri = __shfl_sync(0xffffffffu, r, i);
        int   ci = __shfl_sync(0xffffffffu, c, i);
        float vi = __shfl_sync(0xffffffffu, v, i);
        if (ri != cur) {
            float* dst = &y[(size_t)cur * OUT_F + f];
            atomicAdd(dst, acc.x);
            atomicAdd(dst + 1, acc.y);
            acc = make_float2(0.f, 0.f);
            cur = ri;
        }
        float2 xv = *reinterpret_cast<const float2*>(&x[(size_t)ci * OUT_F + f]);
        acc.x = fmaf(vi, xv.x, acc.x);
        acc.y = fmaf(vi, xv.y, acc.y);
    }
    float* dst = &y[(size_t)cur * OUT_F + f];
    atomicAdd(dst, acc.x);
    atomicAdd(dst + 1, acc.y);
}

// ---------------------------------------------------------------------------
extern "C" void kernel_launch(void* const* d_in, const int* in_sizes, int n_in,
                              void* d_out, int out_size)
{
    const float* features = (const float*)d_in[0];   // [N, 256]
    const float* weight   = (const float*)d_in[1];   // [256, 64]
    const int*   adj_rows = (const int*)d_in[2];     // [E] sorted
    const int*   adj_cols = (const int*)d_in[3];     // [E]
    const float* adj_vals = (const float*)d_in[4];   // [E]
    const int*   active   = (const int*)d_in[5];     // scalar

    const int M  = in_sizes[0] / IN_F;               // 100000
    const int nE = in_sizes[2];                      // 1600000

    float* out_first  = (float*)d_out;                          // output [N,64]
    float* out_second = (float*)d_out + (size_t)M * OUT_F;      // az     [N,64]

    float* support = nullptr;
    cudaGetSymbolAddress((void**)&support, g_support);

    cudaFuncSetAttribute(gemm_mma_kernel,
                         cudaFuncAttributeMaxDynamicSharedMemorySize, SM_TOTAL_G);

    // zero both output halves (atomics accumulate into them)
    cudaMemsetAsync(d_out, 0, (size_t)out_size * sizeof(float), 0);

    // 1) support = tanh(features @ weight)   [mma.sync bf16 3-split]
    int gblocks = (M + TILE_M - 1) / TILE_M;
    gemm_mma_kernel<<<gblocks, 256, SM_TOTAL_G>>>(features, weight, active, support, M);

    // 2) output = adj @ support
    int warps = (nE + 31) / 32;
    int sblocks = (warps * 32 + 255) / 256;
    spmm_kernel<<<sblocks, 256>>>(adj_rows, adj_cols, adj_vals, support, out_first, nE);

    // 3) az = adj @ output
    spmm_kernel<<<sblocks, 256>>>(adj_rows, adj_cols, adj_vals, out_first, out_second, nE);
}

// round 6
// speedup vs baseline: 1.5735x; 1.0685x over previous
#include <cuda_runtime.h>
#include <cuda_bf16.h>
#include <stdint.h>

#define N_NODES 100000
#define IN_F 256
#define OUT_F 64

// Scratch: support = tanh(features @ weight)  [N, 64], and CSR row pointers.
__device__ float g_support[(size_t)N_NODES * OUT_F];
__device__ int   g_row_ptr[N_NODES + 1];

// ===========================================================================
// GEMM + tanh via mma.sync bf16 3-product split (unchanged from R5 — 54.5us).
// ===========================================================================
#define TILE_M 128
#define BKC 128
#define A_ROW_BYTES 272
#define A_PART (TILE_M * A_ROW_BYTES)
#define W_PART (8 * 8 * 32 * 8)
#define SM_AHI 0
#define SM_ALO (SM_AHI + A_PART)
#define SM_WHI (SM_ALO + A_PART)
#define SM_WLO (SM_WHI + W_PART)
#define SM_TOTAL_G (SM_WLO + W_PART)

__device__ __forceinline__ uint32_t smem_u32(const void* p) {
    uint32_t a;
    asm("{ .reg .u64 t; cvta.to.shared.u64 t, %1; cvt.u32.u64 %0, t; }"
        : "=r"(a) : "l"(p));
    return a;
}

#define LDSM_X4(r, addr) \
    asm volatile("ldmatrix.sync.aligned.m8n8.x4.shared.b16 {%0,%1,%2,%3}, [%4];" \
        : "=r"((r)[0]), "=r"((r)[1]), "=r"((r)[2]), "=r"((r)[3]) : "r"(addr))

#define MMA_BF16(d, a, b0, b1) \
    asm volatile("mma.sync.aligned.m16n8k16.row.col.f32.bf16.bf16.f32 " \
        "{%0,%1,%2,%3}, {%4,%5,%6,%7}, {%8,%9}, {%0,%1,%2,%3};" \
        : "+f"((d)[0]), "+f"((d)[1]), "+f"((d)[2]), "+f"((d)[3]) \
        : "r"((a)[0]), "r"((a)[1]), "r"((a)[2]), "r"((a)[3]), "r"(b0), "r"(b1))

__device__ __forceinline__ uint32_t pack_hi2(float x, float y) {
    __nv_bfloat16 hx = __float2bfloat16(x), hy = __float2bfloat16(y);
    return (uint32_t)__bfloat16_as_ushort(hx) |
           ((uint32_t)__bfloat16_as_ushort(hy) << 16);
}
__device__ __forceinline__ uint32_t pack_lo2(float x, float y) {
    __nv_bfloat16 hx = __float2bfloat16(x), hy = __float2bfloat16(y);
    __nv_bfloat16 lx = __float2bfloat16(x - __bfloat162float(hx));
    __nv_bfloat16 ly = __float2bfloat16(y - __bfloat162float(hy));
    return (uint32_t)__bfloat16_as_ushort(lx) |
           ((uint32_t)__bfloat16_as_ushort(ly) << 16);
}

__global__ __launch_bounds__(256, 2) void gemm_mma_kernel(
    const float* __restrict__ A, const float* __restrict__ W,
    const int* __restrict__ active, float* __restrict__ C, int M)
{
    extern __shared__ char sm[];
    const uint32_t sb = smem_u32(sm);
    const int tid = threadIdx.x;
    const int wid = tid >> 5;
    const int lane = tid & 31;
    const int row0 = blockIdx.x * TILE_M;

    float d[8][4];
    #pragma unroll
    for (int j = 0; j < 8; j++)
        #pragma unroll
        for (int e = 0; e < 4; e++) d[j][e] = 0.f;

    const uint32_t a_lm_base =
        sb + SM_AHI + (uint32_t)(wid * 16 + (lane & 15)) * A_ROW_BYTES
        + (uint32_t)((lane >> 4) * 16);

    #pragma unroll
    for (int kc = 0; kc < 2; kc++) {
        const int kbase = kc * BKC;

        #pragma unroll
        for (int i = 0; i < 16; i++) {
            int idx = tid + i * 256;
            int r = idx >> 5;
            int q = idx & 31;
            int gr = row0 + r;
            float4 v = make_float4(0.f, 0.f, 0.f, 0.f);
            if (gr < M)
                v = *reinterpret_cast<const float4*>(
                    &A[(size_t)gr * IN_F + kbase + (q << 2)]);
            uint2 hp = make_uint2(pack_hi2(v.x, v.y), pack_hi2(v.z, v.w));
            uint2 lp = make_uint2(pack_lo2(v.x, v.y), pack_lo2(v.z, v.w));
            int off = r * A_ROW_BYTES + q * 8;
            *reinterpret_cast<uint2*>(sm + SM_AHI + off) = hp;
            *reinterpret_cast<uint2*>(sm + SM_ALO + off) = lp;
        }

        #pragma unroll
        for (int i = 0; i < 8; i++) {
            int idx = tid + i * 256;
            int t = idx & 31;
            int j = (idx >> 5) & 7;
            int s = idx >> 8;
            int k = kbase + s * 16 + (t & 3) * 2;
            int n = j * 8 + (t >> 2);
            float w00 = W[(size_t)k * OUT_F + n];
            float w01 = W[(size_t)(k + 1) * OUT_F + n];
            float w10 = W[(size_t)(k + 8) * OUT_F + n];
            float w11 = W[(size_t)(k + 9) * OUT_F + n];
            *reinterpret_cast<uint2*>(sm + SM_WHI + idx * 8) =
                make_uint2(pack_hi2(w00, w01), pack_hi2(w10, w11));
            *reinterpret_cast<uint2*>(sm + SM_WLO + idx * 8) =
                make_uint2(pack_lo2(w00, w01), pack_lo2(w10, w11));
        }
        __syncthreads();

        #pragma unroll
        for (int s = 0; s < 8; s++) {
            uint32_t ah[4], al[4];
            LDSM_X4(ah, a_lm_base + s * 32);
            LDSM_X4(al, a_lm_base + s * 32 + (SM_ALO - SM_AHI));
            const char* whb = sm + SM_WHI + (s * 8 * 32 + lane) * 8;
            const char* wlb = sm + SM_WLO + (s * 8 * 32 + lane) * 8;
            #pragma unroll
            for (int j = 0; j < 8; j++) {
                uint2 bh = *reinterpret_cast<const uint2*>(whb + j * 256);
                uint2 bl = *reinterpret_cast<const uint2*>(wlb + j * 256);
                MMA_BF16(d[j], ah, bh.x, bh.y);
                MMA_BF16(d[j], al, bh.x, bh.y);
                MMA_BF16(d[j], ah, bl.x, bl.y);
            }
        }
        __syncthreads();
    }

    const int act = *active;
    int rlo = row0 + wid * 16 + (lane >> 2);
    int col = (lane & 3) * 2;
    #pragma unroll
    for (int j = 0; j < 8; j++) {
        float2 p0 = make_float2(d[j][0], d[j][1]);
        float2 p1 = make_float2(d[j][2], d[j][3]);
        if (act) {
            p0.x = tanhf(p0.x); p0.y = tanhf(p0.y);
            p1.x = tanhf(p1.x); p1.y = tanhf(p1.y);
        }
        if (rlo < M)
            *reinterpret_cast<float2*>(&C[(size_t)rlo * OUT_F + j * 8 + col]) = p0;
        if (rlo + 8 < M)
            *reinterpret_cast<float2*>(&C[(size_t)(rlo + 8) * OUT_F + j * 8 + col]) = p1;
    }
}

// ---------------------------------------------------------------------------
// Build CSR row_ptr from sorted COO rows. Covers leading gap, internal gaps,
// and the tail, so every entry is (re)written deterministically each call.
// ---------------------------------------------------------------------------
__global__ __launch_bounds__(256) void build_rowptr_kernel(
    const int* __restrict__ rows, int nE, int nRows, int* __restrict__ rp)
{
    int e = blockIdx.x * blockDim.x + threadIdx.x;
    if (e >= nE) return;
    int r = rows[e];
    int rprev = (e == 0) ? -1 : rows[e - 1];
    for (int q = rprev + 1; q <= r; q++) rp[q] = e;
    if (e == nE - 1) {
        for (int q = r + 1; q <= nRows; q++) rp[q] = nE;
    }
}

// ---------------------------------------------------------------------------
// Row-parallel SpMM: one warp per output row, NO atomics, NO memset needed.
// Lanes stage <=32 (col,val) pairs, shfl-broadcast each edge, gather
// x[col] (float2 per lane = coalesced 256B row), accumulate, one STG.64.
// ---------------------------------------------------------------------------
__global__ __launch_bounds__(256) void spmm_row_kernel(
    const int* __restrict__ rp, const int* __restrict__ cols,
    const float* __restrict__ vals, const float* __restrict__ x,
    float* __restrict__ y, int nRows)
{
    const int row = (blockIdx.x * blockDim.x + threadIdx.x) >> 5;
    const int lane = threadIdx.x & 31;
    if (row >= nRows) return;

    const int s = rp[row];
    const int e = rp[row + 1];
    const int f = lane << 1;
    float2 acc = make_float2(0.f, 0.f);

    for (int base = s; base < e; base += 32) {
        const int n = min(32, e - base);
        int   c = (lane < n) ? cols[base + lane] : 0;
        float v = (lane < n) ? vals[base + lane] : 0.f;
        for (int i = 0; i < n; i++) {
            int   ci = __shfl_sync(0xffffffffu, c, i);
            float vi = __shfl_sync(0xffffffffu, v, i);
            float2 xv = *reinterpret_cast<const float2*>(&x[(size_t)ci * OUT_F + f]);
            acc.x = fmaf(vi, xv.x, acc.x);
            acc.y = fmaf(vi, xv.y, acc.y);
        }
    }
    *reinterpret_cast<float2*>(&y[(size_t)row * OUT_F + f]) = acc;
}

// ---------------------------------------------------------------------------
extern "C" void kernel_launch(void* const* d_in, const int* in_sizes, int n_in,
                              void* d_out, int out_size)
{
    const float* features = (const float*)d_in[0];   // [N, 256]
    const float* weight   = (const float*)d_in[1];   // [256, 64]
    const int*   adj_rows = (const int*)d_in[2];     // [E] sorted
    const int*   adj_cols = (const int*)d_in[3];     // [E]
    const float* adj_vals = (const float*)d_in[4];   // [E]
    const int*   active   = (const int*)d_in[5];     // scalar

    const int M  = in_sizes[0] / IN_F;               // 100000
    const int nE = in_sizes[2];                      // 1600000

    float* out_first  = (float*)d_out;                          // output [N,64]
    float* out_second = (float*)d_out + (size_t)M * OUT_F;      // az     [N,64]

    float* support = nullptr;
    cudaGetSymbolAddress((void**)&support, g_support);
    int* row_ptr = nullptr;
    cudaGetSymbolAddress((void**)&row_ptr, g_row_ptr);

    cudaFuncSetAttribute(gemm_mma_kernel,
                         cudaFuncAttributeMaxDynamicSharedMemorySize, SM_TOTAL_G);

    // 0) CSR row pointers (cheap, overlaps conceptually with nothing it needs)
    build_rowptr_kernel<<<(nE + 255) / 256, 256>>>(adj_rows, nE, M, row_ptr);

    // 1) support = tanh(features @ weight)   [mma.sync bf16 3-split]
    int gblocks = (M + TILE_M - 1) / TILE_M;
    gemm_mma_kernel<<<gblocks, 256, SM_TOTAL_G>>>(features, weight, active, support, M);

    // 2) output = adj @ support   (row-parallel, no atomics)
    int sblocks = (M * 32 + 255) / 256;
    spmm_row_kernel<<<sblocks, 256>>>(row_ptr, adj_cols, adj_vals, support, out_first, M);

    // 3) az = adj @ output
    spmm_row_kernel<<<sblocks, 256>>>(row_ptr, adj_cols, adj_vals, out_first, out_second, M);
}

// round 7
// speedup vs baseline: 1.8147x; 1.1533x over previous
#include <cuda_runtime.h>
#include <cuda_bf16.h>
#include <stdint.h>

#define N_NODES 100000
#define IN_F 256
#define OUT_F 64

// Scratch: support, CSR row pointers, pre-packed W fragments.
__device__ float g_support[(size_t)N_NODES * OUT_F];
__device__ int   g_row_ptr[N_NODES + 1];
__device__ uint2 g_wfrag_hi[2][2048];
__device__ uint2 g_wfrag_lo[2][2048];

// ===========================================================================
// Common helpers
// ===========================================================================
__device__ __forceinline__ uint32_t smem_u32(const void* p) {
    uint32_t a;
    asm("{ .reg .u64 t; cvta.to.shared.u64 t, %1; cvt.u32.u64 %0, t; }"
        : "=r"(a) : "l"(p));
    return a;
}

#define LDSM_X4(r, addr) \
    asm volatile("ldmatrix.sync.aligned.m8n8.x4.shared.b16 {%0,%1,%2,%3}, [%4];" \
        : "=r"((r)[0]), "=r"((r)[1]), "=r"((r)[2]), "=r"((r)[3]) : "r"(addr))

#define MMA_BF16(d, a, b0, b1) \
    asm volatile("mma.sync.aligned.m16n8k16.row.col.f32.bf16.bf16.f32 " \
        "{%0,%1,%2,%3}, {%4,%5,%6,%7}, {%8,%9}, {%0,%1,%2,%3};" \
        : "+f"((d)[0]), "+f"((d)[1]), "+f"((d)[2]), "+f"((d)[3]) \
        : "r"((a)[0]), "r"((a)[1]), "r"((a)[2]), "r"((a)[3]), "r"(b0), "r"(b1))

// Split pair (x,y) -> packed bf16x2 hi (truncated) + packed bf16x2 lo (rounded).
// hi via PRMT (top halves), lo = round(x - hi_x) exact-residual capture.
__device__ __forceinline__ uint32_t split2(float x, float y, uint32_t& lo2) {
    uint32_t bx = __float_as_uint(x), by = __float_as_uint(y), hp;
    asm("prmt.b32 %0, %1, %2, 0x7632;" : "=r"(hp) : "r"(bx), "r"(by));
    float hx = __uint_as_float(bx & 0xFFFF0000u);
    float hy = __uint_as_float(by & 0xFFFF0000u);
    float lx = x - hx, ly = y - hy;
    asm("cvt.rn.bf16x2.f32 %0, %1, %2;" : "=r"(lo2) : "f"(ly), "f"(lx));
    return hp;
}

// ===========================================================================
// One-shot W fragment packer: 2 k-chunks x 2048 fragment uint2 (hi & lo).
// Fragment (s,j,t): b0={W[k][n],W[k+1][n]}, b1={W[k+8][n],W[k+9][n]},
//   k = kc*128 + s*16 + (t&3)*2 ; n = j*8 + (t>>2)
// ===========================================================================
__global__ __launch_bounds__(256) void pack_w_kernel(const float* __restrict__ W)
{
    int idx = blockIdx.x * 256 + threadIdx.x;   // 0..4095
    int kc = idx >> 11;
    int id = idx & 2047;
    int t = id & 31;
    int j = (id >> 5) & 7;
    int s = id >> 8;
    int k = kc * 128 + s * 16 + (t & 3) * 2;
    int n = j * 8 + (t >> 2);
    float w00 = W[(size_t)k * OUT_F + n];
    float w01 = W[(size_t)(k + 1) * OUT_F + n];
    float w10 = W[(size_t)(k + 8) * OUT_F + n];
    float w11 = W[(size_t)(k + 9) * OUT_F + n];
    uint32_t l0, l1;
    uint32_t h0 = split2(w00, w01, l0);
    uint32_t h1 = split2(w10, w11, l1);
    g_wfrag_hi[kc][id] = make_uint2(h0, h1);
    g_wfrag_lo[kc][id] = make_uint2(l0, l1);
}

// ===========================================================================
// GEMM + tanh via mma.sync bf16 3-product split.
// W fragments pre-packed (copied linearly into smem); A split via PRMT.
// ===========================================================================
#define TILE_M 128
#define BKC 128
#define A_ROW_BYTES 272
#define A_PART (TILE_M * A_ROW_BYTES)
#define W_PART (8 * 8 * 32 * 8)
#define SM_AHI 0
#define SM_ALO (SM_AHI + A_PART)
#define SM_WHI (SM_ALO + A_PART)
#define SM_WLO (SM_WHI + W_PART)
#define SM_TOTAL_G (SM_WLO + W_PART)

__global__ __launch_bounds__(256, 2) void gemm_mma_kernel(
    const float* __restrict__ A,
    const int* __restrict__ active, float* __restrict__ C, int M)
{
    extern __shared__ char sm[];
    const uint32_t sb = smem_u32(sm);
    const int tid = threadIdx.x;
    const int wid = tid >> 5;
    const int lane = tid & 31;
    const int row0 = blockIdx.x * TILE_M;

    float d[8][4];
    #pragma unroll
    for (int j = 0; j < 8; j++)
        #pragma unroll
        for (int e = 0; e < 4; e++) d[j][e] = 0.f;

    const uint32_t a_lm_base =
        sb + SM_AHI + (uint32_t)(wid * 16 + (lane & 15)) * A_ROW_BYTES
        + (uint32_t)((lane >> 4) * 16);

    #pragma unroll
    for (int kc = 0; kc < 2; kc++) {
        const int kbase = kc * BKC;

        // ---- A chunk: 128 x 128 fp32 -> hi/lo bf16 (PRMT split) ----
        #pragma unroll
        for (int i = 0; i < 16; i++) {
            int idx = tid + i * 256;
            int r = idx >> 5;
            int q = idx & 31;
            int gr = row0 + r;
            float4 v = make_float4(0.f, 0.f, 0.f, 0.f);
            if (gr < M)
                v = *reinterpret_cast<const float4*>(
                    &A[(size_t)gr * IN_F + kbase + (q << 2)]);
            uint32_t l0, l1;
            uint32_t h0 = split2(v.x, v.y, l0);
            uint32_t h1 = split2(v.z, v.w, l1);
            int off = r * A_ROW_BYTES + q * 8;
            *reinterpret_cast<uint2*>(sm + SM_AHI + off) = make_uint2(h0, h1);
            *reinterpret_cast<uint2*>(sm + SM_ALO + off) = make_uint2(l0, l1);
        }

        // ---- W chunk: linear copy of pre-packed fragments ----
        {
            const uint2* wh = g_wfrag_hi[kc];
            const uint2* wl = g_wfrag_lo[kc];
            uint2* dh = reinterpret_cast<uint2*>(sm + SM_WHI);
            uint2* dl = reinterpret_cast<uint2*>(sm + SM_WLO);
            #pragma unroll
            for (int i = 0; i < 8; i++) {
                int idx = tid + i * 256;
                dh[idx] = wh[idx];
                dl[idx] = wl[idx];
            }
        }
        __syncthreads();

        // ---- MMA: 8 k16-steps x (hi*hi + lo*hi + hi*lo) ----
        #pragma unroll
        for (int s = 0; s < 8; s++) {
            uint32_t ah[4], al[4];
            LDSM_X4(ah, a_lm_base + s * 32);
            LDSM_X4(al, a_lm_base + s * 32 + (SM_ALO - SM_AHI));
            const char* whb = sm + SM_WHI + (s * 8 * 32 + lane) * 8;
            const char* wlb = sm + SM_WLO + (s * 8 * 32 + lane) * 8;
            #pragma unroll
            for (int j = 0; j < 8; j++) {
                uint2 bh = *reinterpret_cast<const uint2*>(whb + j * 256);
                uint2 bl = *reinterpret_cast<const uint2*>(wlb + j * 256);
                MMA_BF16(d[j], ah, bh.x, bh.y);
                MMA_BF16(d[j], al, bh.x, bh.y);
                MMA_BF16(d[j], ah, bl.x, bl.y);
            }
        }
        __syncthreads();
    }

    // ---- epilogue: tanh + store ----
    const int act = *active;
    int rlo = row0 + wid * 16 + (lane >> 2);
    int col = (lane & 3) * 2;
    #pragma unroll
    for (int j = 0; j < 8; j++) {
        float2 p0 = make_float2(d[j][0], d[j][1]);
        float2 p1 = make_float2(d[j][2], d[j][3]);
        if (act) {
            p0.x = tanhf(p0.x); p0.y = tanhf(p0.y);
            p1.x = tanhf(p1.x); p1.y = tanhf(p1.y);
        }
        if (rlo < M)
            *reinterpret_cast<float2*>(&C[(size_t)rlo * OUT_F + j * 8 + col]) = p0;
        if (rlo + 8 < M)
            *reinterpret_cast<float2*>(&C[(size_t)(rlo + 8) * OUT_F + j * 8 + col]) = p1;
    }
}

// ---------------------------------------------------------------------------
// Build CSR row_ptr from sorted COO rows (covers gaps + tail, deterministic).
// ---------------------------------------------------------------------------
__global__ __launch_bounds__(256) void build_rowptr_kernel(
    const int* __restrict__ rows, int nE, int nRows, int* __restrict__ rp)
{
    int e = blockIdx.x * blockDim.x + threadIdx.x;
    if (e >= nE) return;
    int r = rows[e];
    int rprev = (e == 0) ? -1 : rows[e - 1];
    for (int q = rprev + 1; q <= r; q++) rp[q] = e;
    if (e == nE - 1) {
        for (int q = r + 1; q <= nRows; q++) rp[q] = nE;
    }
}

// ---------------------------------------------------------------------------
// Row-parallel SpMM, half-warp per edge: warp owns one output row; each
// half-warp (16 lanes x float4 = 256B) gathers one full x-row per step, so
// two edges are in flight per iteration with NO shfl in the inner loop.
// Halves combined once per row via 4x shfl_xor(16). No atomics, no memset.
// ---------------------------------------------------------------------------
__global__ __launch_bounds__(256) void spmm_row_kernel(
    const int* __restrict__ rp, const int* __restrict__ cols,
    const float* __restrict__ vals, const float* __restrict__ x,
    float* __restrict__ y, int nRows)
{
    const int row = (blockIdx.x * blockDim.x + threadIdx.x) >> 5;
    if (row >= nRows) return;
    const int lane = threadIdx.x & 31;
    const int half = lane >> 4;      // which edge of the pair
    const int fl = (lane & 15) << 2; // feature quad

    const int s = rp[row];
    const int e = rp[row + 1];

    float4 acc = make_float4(0.f, 0.f, 0.f, 0.f);
    int b = s + half;
    // 2x unroll: 4 edges in flight per warp iteration
    for (; b + 2 < e; b += 4) {
        int   c0 = __ldg(&cols[b]);
        float v0 = __ldg(&vals[b]);
        int   c1 = __ldg(&cols[b + 2]);
        float v1 = __ldg(&vals[b + 2]);
        float4 x0 = *reinterpret_cast<const float4*>(&x[(size_t)c0 * OUT_F + fl]);
        float4 x1 = *reinterpret_cast<const float4*>(&x[(size_t)c1 * OUT_F + fl]);
        acc.x = fmaf(v0, x0.x, acc.x); acc.y = fmaf(v0, x0.y, acc.y);
        acc.z = fmaf(v0, x0.z, acc.z); acc.w = fmaf(v0, x0.w, acc.w);
        acc.x = fmaf(v1, x1.x, acc.x); acc.y = fmaf(v1, x1.y, acc.y);
        acc.z = fmaf(v1, x1.z, acc.z); acc.w = fmaf(v1, x1.w, acc.w);
    }
    if (b < e) {
        int   c = __ldg(&cols[b]);
        float v = __ldg(&vals[b]);
        float4 xv = *reinterpret_cast<const float4*>(&x[(size_t)c * OUT_F + fl]);
        acc.x = fmaf(v, xv.x, acc.x); acc.y = fmaf(v, xv.y, acc.y);
        acc.z = fmaf(v, xv.z, acc.z); acc.w = fmaf(v, xv.w, acc.w);
    }

    acc.x += __shfl_xor_sync(0xffffffffu, acc.x, 16);
    acc.y += __shfl_xor_sync(0xffffffffu, acc.y, 16);
    acc.z += __shfl_xor_sync(0xffffffffu, acc.z, 16);
    acc.w += __shfl_xor_sync(0xffffffffu, acc.w, 16);

    if (half == 0)
        *reinterpret_cast<float4*>(&y[(size_t)row * OUT_F + fl]) = acc;
}

// ---------------------------------------------------------------------------
extern "C" void kernel_launch(void* const* d_in, const int* in_sizes, int n_in,
                              void* d_out, int out_size)
{
    const float* features = (const float*)d_in[0];   // [N, 256]
    const float* weight   = (const float*)d_in[1];   // [256, 64]
    const int*   adj_rows = (const int*)d_in[2];     // [E] sorted
    const int*   adj_cols = (const int*)d_in[3];     // [E]
    const float* adj_vals = (const float*)d_in[4];   // [E]
    const int*   active   = (const int*)d_in[5];     // scalar

    const int M  = in_sizes[0] / IN_F;               // 100000
    const int nE = in_sizes[2];                      // 1600000

    float* out_first  = (float*)d_out;                          // output [N,64]
    float* out_second = (float*)d_out + (size_t)M * OUT_F;      // az     [N,64]

    float* support = nullptr;
    cudaGetSymbolAddress((void**)&support, g_support);
    int* row_ptr = nullptr;
    cudaGetSymbolAddress((void**)&row_ptr, g_row_ptr);

    cudaFuncSetAttribute(gemm_mma_kernel,
                         cudaFuncAttributeMaxDynamicSharedMemorySize, SM_TOTAL_G);

    // 0) pre-pack W fragments + build CSR row pointers (both tiny)
    pack_w_kernel<<<16, 256>>>(weight);
    build_rowptr_kernel<<<(nE + 255) / 256, 256>>>(adj_rows, nE, M, row_ptr);

    // 1) support = tanh(features @ weight)
    int gblocks = (M + TILE_M - 1) / TILE_M;
    gemm_mma_kernel<<<gblocks, 256, SM_TOTAL_G>>>(features, active, support, M);

    // 2) output = adj @ support
    int sblocks = (M * 32 + 255) / 256;
    spmm_row_kernel<<<sblocks, 256>>>(row_ptr, adj_cols, adj_vals, support, out_first, M);

    // 3) az = adj @ output
    spmm_row_kernel<<<sblocks, 256>>>(row_ptr, adj_cols, adj_vals, out_first, out_second, M);
}